// round 5
// baseline (speedup 1.0000x reference)
#include <cuda_runtime.h>
#include <cstdint>

// Problem constants (fixed by reference)
#define BATCH   4
#define NTOK    8192
#define DIM     768
#define SEGW    512
#define NSEG    16
#define MG      256       // gathered (even) rows per segment
#define TM      32        // Q rows per CTA tile
#define NTILE   (MG/TM)   // 8 tiles per problem
#define KC      32        // phase-1 k-chunk width
#define NCHUNK  (DIM/KC)  // 24
#define THREADS 256

#define DHALF   384       // phase-3 d half-width
#define KSLAB   8         // phase-3 V slab rows
#define NSLAB   (MG/KSLAB)// 32

// Padded smem strides (floats). k-major: stride%8==4 (frag loads spread 4*ln4+lc4);
// V n-major: stride%32==8 (lc4*8+ln4 spreads all 32 banks).
#define K_STRIDE 36
#define P_STRIDE 260
#define V_STRIDE 392      // 384 + 8

#define KCHF    (MG*K_STRIDE)     // 9216 floats per K buffer
#define P_OFF   0                 // P (32x260=8320f) overlaps K buffers (dead by then)
#define V_OFF   (2*KCHF)          // 18432
#define VSLABF  (KSLAB*V_STRIDE)  // 3136 floats per V buffer
#define SMEM_FLOATS (V_OFF + 2*VSLABF)      // 24704
#define SMEM_BYTES  (SMEM_FLOATS * 4)       // 98816  (2 CTAs = 193KB <= 228KB)

__device__ __forceinline__ uint32_t f2tf32(float f) {
    uint32_t u;
    asm("cvt.rna.tf32.f32 %0, %1;" : "=r"(u) : "f"(f));
    return u;
}

__device__ __forceinline__ void sts_tf32x4(float* dst, float4 v) {
    float4 w;
    w.x = __uint_as_float(f2tf32(v.x));
    w.y = __uint_as_float(f2tf32(v.y));
    w.z = __uint_as_float(f2tf32(v.z));
    w.w = __uint_as_float(f2tf32(v.w));
    *(float4*)dst = w;
}

__device__ __forceinline__ void mma8(float c[4], const uint32_t a[4], const uint32_t b[2]) {
    asm volatile(
        "mma.sync.aligned.m16n8k8.row.col.f32.tf32.tf32.f32 "
        "{%0,%1,%2,%3}, {%4,%5,%6,%7}, {%8,%9}, {%0,%1,%2,%3};\n"
        : "+f"(c[0]), "+f"(c[1]), "+f"(c[2]), "+f"(c[3])
        : "r"(a[0]), "r"(a[1]), "r"(a[2]), "r"(a[3]), "r"(b[0]), "r"(b[1]));
}

__global__ __launch_bounds__(THREADS, 2)
void dilated_attn_kernel(const float* __restrict__ x, float* __restrict__ y)
{
    extern __shared__ float sm[];
    uint32_t* smu = (uint32_t*)sm;
    const int tid  = threadIdx.x;
    const int lane = tid & 31;
    const int wid  = tid >> 5;

    const int tile = blockIdx.x & (NTILE - 1);   // 8 row tiles of 32 per problem
    const int pid  = blockIdx.x >> 3;            // 64 problems
    const int b    = pid >> 4;
    const int seg  = pid & 15;

    const long segbase = (long)b * NTOK + (long)seg * SEGW;  // token base
    const int  q0 = tile * TM;

    const int ln4 = lane >> 2;   // fragment group 0..7
    const int lc4 = lane & 3;    // thread-in-group 0..3

    // ============ Phase 1: S = Q K^T (32 x 256), double-buffered K chunks ============
    // Warp layout: 1 m-warp x 8 n-warps; warp covers 32 cols (nt=4), both 16-row halves.
    float acc[2][4][4];
    #pragma unroll
    for (int mt = 0; mt < 2; mt++)
        #pragma unroll
        for (int nt = 0; nt < 4; nt++)
            #pragma unroll
            for (int i = 0; i < 4; i++)
                acc[mt][nt][i] = 0.f;

    // Prologue: chunk 0 -> buf0 (tf32-rounded at store)
    #pragma unroll
    for (int j = 0; j < 8; j++) {
        int idx = j * THREADS + tid;
        int r = idx >> 3, c4 = idx & 7;
        float4 v = *(const float4*)(x + (size_t)(segbase + 2 * r) * DIM + c4 * 4);
        sts_tf32x4(sm + r * K_STRIDE + c4 * 4, v);
    }
    __syncthreads();

    float4 stg[8];
    for (int kc = 0; kc < NCHUNK; kc++) {
        const uint32_t* cur = smu + (kc & 1 ? KCHF : 0);
        const bool pf = (kc + 1 < NCHUNK);
        if (pf) {
            const int kd = (kc + 1) * KC;
            #pragma unroll
            for (int j = 0; j < 8; j++) {
                int idx = j * THREADS + tid;
                int r = idx >> 3, c4 = idx & 7;
                stg[j] = *(const float4*)(x + (size_t)(segbase + 2 * r) * DIM + kd + c4 * 4);
            }
        }
        const uint32_t* abase = cur + (q0 + ln4) * K_STRIDE + lc4;
        const uint32_t* bbase = cur + (wid * 32 + ln4) * K_STRIDE + lc4;
        #pragma unroll
        for (int ks = 0; ks < KC / 8; ks++) {
            const int kk = ks * 8;
            uint32_t a[2][4];
            #pragma unroll
            for (int mt = 0; mt < 2; mt++) {
                const uint32_t* ba = abase + mt * 16 * K_STRIDE + kk;
                a[mt][0] = ba[0];
                a[mt][1] = ba[8 * K_STRIDE];
                a[mt][2] = ba[4];
                a[mt][3] = ba[8 * K_STRIDE + 4];
            }
            #pragma unroll
            for (int nt = 0; nt < 4; nt++) {
                const uint32_t* bb = bbase + nt * 8 * K_STRIDE + kk;
                uint32_t bf[2] = { bb[0], bb[4] };
                mma8(acc[0][nt], a[0], bf);
                mma8(acc[1][nt], a[1], bf);
            }
        }
        if (pf) {
            float* dst = sm + (kc & 1 ? 0 : KCHF);
            #pragma unroll
            for (int j = 0; j < 8; j++) {
                int idx = j * THREADS + tid;
                int r = idx >> 3, c4 = idx & 7;
                sts_tf32x4(dst + r * K_STRIDE + c4 * 4, stg[j]);
            }
        }
        __syncthreads();
    }

    // ============ Phase 2: scale + softmax into P (tf32-rounded on final write) ============
    const float scale = 0.03608439182435161f;  // 768^-0.5
    #pragma unroll
    for (int mt = 0; mt < 2; mt++)
        #pragma unroll
        for (int nt = 0; nt < 4; nt++) {
            int r = mt * 16 + ln4;
            int c = wid * 32 + nt * 8 + 2 * lc4;
            sm[P_OFF + r * P_STRIDE + c]           = acc[mt][nt][0] * scale;
            sm[P_OFF + r * P_STRIDE + c + 1]       = acc[mt][nt][1] * scale;
            sm[P_OFF + (r + 8) * P_STRIDE + c]     = acc[mt][nt][2] * scale;
            sm[P_OFF + (r + 8) * P_STRIDE + c + 1] = acc[mt][nt][3] * scale;
        }
    __syncthreads();

    // Row softmax: warp w handles rows w*4..w*4+3
    #pragma unroll
    for (int rr = 0; rr < 4; rr++) {
        int row = wid * 4 + rr;
        float* pr = sm + P_OFF + row * P_STRIDE;
        float v[8];
        float mx = -1e30f;
        #pragma unroll
        for (int i = 0; i < 8; i++) { v[i] = pr[lane + 32 * i]; mx = fmaxf(mx, v[i]); }
        #pragma unroll
        for (int o = 16; o > 0; o >>= 1) mx = fmaxf(mx, __shfl_xor_sync(~0u, mx, o));
        float s = 0.f;
        #pragma unroll
        for (int i = 0; i < 8; i++) { v[i] = expf(v[i] - mx); s += v[i]; }
        #pragma unroll
        for (int o = 16; o > 0; o >>= 1) s += __shfl_xor_sync(~0u, s, o);
        float inv = 1.f / s;
        #pragma unroll
        for (int i = 0; i < 8; i++)
            pr[lane + 32 * i] = __uint_as_float(f2tf32(v[i] * inv));
    }
    __syncthreads();

    // ============ Phase 3: out = P V, two d-halves, V streamed in 8-row slabs ============
    // Warp layout: 1 m x 8 n; warp covers 48 cols (nt=6), both 16-row halves.
    for (int half = 0; half < 2; half++) {
        const int d0 = half * DHALF;

        float o[2][6][4];
        #pragma unroll
        for (int mt = 0; mt < 2; mt++)
            #pragma unroll
            for (int nt = 0; nt < 6; nt++)
                #pragma unroll
                for (int i = 0; i < 4; i++)
                    o[mt][nt][i] = 0.f;

        // Prologue: slab 0 -> V buf0
        #pragma unroll
        for (int j = 0; j < 3; j++) {
            int idx = j * THREADS + tid;
            int row = idx / 96, c4 = idx % 96;
            float4 v = *(const float4*)(x + (size_t)(segbase + 2 * row) * DIM + d0 + c4 * 4);
            sts_tf32x4(sm + V_OFF + row * V_STRIDE + c4 * 4, v);
        }
        __syncthreads();

        float4 vst[3];
        for (int sl = 0; sl < NSLAB; sl++) {
            const uint32_t* vcur = smu + V_OFF + (sl & 1) * VSLABF;
            const bool pf = (sl + 1 < NSLAB);
            if (pf) {
                const int rbase = (sl + 1) * KSLAB;
                #pragma unroll
                for (int j = 0; j < 3; j++) {
                    int idx = j * THREADS + tid;
                    int row = idx / 96, c4 = idx % 96;
                    vst[j] = *(const float4*)(x + (size_t)(segbase + 2 * (rbase + row)) * DIM + d0 + c4 * 4);
                }
            }
            {
                const int kg = sl * KSLAB;           // slab = one k8 step
                uint32_t a[2][4];
                const uint32_t* abase = smu + P_OFF + ln4 * P_STRIDE + kg + lc4;
                #pragma unroll
                for (int mt = 0; mt < 2; mt++) {
                    const uint32_t* ba = abase + mt * 16 * P_STRIDE;
                    a[mt][0] = ba[0];
                    a[mt][1] = ba[8 * P_STRIDE];
                    a[mt][2] = ba[4];
                    a[mt][3] = ba[8 * P_STRIDE + 4];
                }
                const uint32_t* bbase = vcur + lc4 * V_STRIDE + wid * 48 + ln4;
                #pragma unroll
                for (int nt = 0; nt < 6; nt++) {
                    const uint32_t* bb = bbase + nt * 8;
                    uint32_t bf[2] = { bb[0], bb[4 * V_STRIDE] };
                    mma8(o[0][nt], a[0], bf);
                    mma8(o[1][nt], a[1], bf);
                }
            }
            if (pf) {
                float* dst = sm + V_OFF + ((sl + 1) & 1) * VSLABF;
                #pragma unroll
                for (int j = 0; j < 3; j++) {
                    int idx = j * THREADS + tid;
                    int row = idx / 96, c4 = idx % 96;
                    sts_tf32x4(dst + row * V_STRIDE + c4 * 4, vst[j]);
                }
            }
            __syncthreads();
        }

        // Epilogue: even (gathered) rows get results
        #pragma unroll
        for (int mt = 0; mt < 2; mt++)
            #pragma unroll
            for (int nt = 0; nt < 6; nt++) {
                int gr = q0 + mt * 16 + ln4;
                int c  = d0 + wid * 48 + nt * 8 + 2 * lc4;
                long tok0 = segbase + 2 * (long)gr;
                long tok1 = segbase + 2 * (long)(gr + 8);
                *(float2*)(y + (size_t)tok0 * DIM + c) = make_float2(o[mt][nt][0], o[mt][nt][1]);
                *(float2*)(y + (size_t)tok1 * DIM + c) = make_float2(o[mt][nt][2], o[mt][nt][3]);
            }

        // Odd partner rows are exactly zero
        for (int j = 0; j < 12; j++) {
            int i = j * THREADS + tid;
            int r = i / 96, c4 = i % 96;
            long tok = segbase + 2 * (long)(q0 + r) + 1;
            *(float4*)(y + (size_t)tok * DIM + d0 + c4 * 4) = make_float4(0.f, 0.f, 0.f, 0.f);
        }
        __syncthreads();
    }
}

extern "C" void kernel_launch(void* const* d_in, const int* in_sizes, int n_in,
                              void* d_out, int out_size)
{
    const float* x = (const float*)d_in[0];
    float* y = (float*)d_out;
    cudaFuncSetAttribute(dilated_attn_kernel,
                         cudaFuncAttributeMaxDynamicSharedMemorySize, SMEM_BYTES);
    dilated_attn_kernel<<<BATCH * NSEG * NTILE, THREADS, SMEM_BYTES>>>(x, y);
}

// round 7
// speedup vs baseline: 1.5125x; 1.5125x over previous
#include <cuda_runtime.h>
#include <cstdint>

// Problem constants (fixed by reference)
#define BATCH   4
#define NTOK    8192
#define DIM     768
#define SEGW    512
#define NSEG    16
#define MG      256       // gathered (even) rows per segment
#define TM      128       // Q rows per CTA tile
#define KC      32        // phase-1 k-chunk width
#define NCHUNK  (DIM/KC)  // 24
#define THREADS 512

#define DCH     192       // phase-3 d chunk width
#define KSLAB   32        // phase-3 V slab rows
#define NSLAB   (MG/KSLAB)// 8

// Padded smem strides (floats). k-major: stride%8==4; V n-major: stride%32==8.
#define K_STRIDE 36
#define P_STRIDE 260
#define V_STRIDE 200      // 192 + 8

#define KCHF    (MG*K_STRIDE)     // 9216 floats per K buffer (2 buffers alias P)
#define P_OFF   0
#define P_FLOATS (TM*P_STRIDE)    // 33280
#define V_OFF   P_FLOATS
#define VSLABF  (KSLAB*V_STRIDE)  // 6400
#define SMEM_FLOATS (V_OFF + 2*VSLABF)   // 46080
#define SMEM_BYTES  (SMEM_FLOATS * 4)    // 184320  (1 CTA/SM)

__device__ __forceinline__ uint32_t f2tf32(float f) {
    uint32_t u;
    asm("cvt.rna.tf32.f32 %0, %1;" : "=r"(u) : "f"(f));
    return u;
}

__device__ __forceinline__ void sts_tf32x4(float* dst, float4 v) {
    float4 w;
    w.x = __uint_as_float(f2tf32(v.x));
    w.y = __uint_as_float(f2tf32(v.y));
    w.z = __uint_as_float(f2tf32(v.z));
    w.w = __uint_as_float(f2tf32(v.w));
    *(float4*)dst = w;
}

__device__ __forceinline__ void mma8(float c[4], const uint32_t a[4], const uint32_t b[2]) {
    asm volatile(
        "mma.sync.aligned.m16n8k8.row.col.f32.tf32.tf32.f32 "
        "{%0,%1,%2,%3}, {%4,%5,%6,%7}, {%8,%9}, {%0,%1,%2,%3};\n"
        : "+f"(c[0]), "+f"(c[1]), "+f"(c[2]), "+f"(c[3])
        : "r"(a[0]), "r"(a[1]), "r"(a[2]), "r"(a[3]), "r"(b[0]), "r"(b[1]));
}

__global__ __launch_bounds__(THREADS, 1)
void dilated_attn_kernel(const float* __restrict__ x, float* __restrict__ y)
{
    extern __shared__ float sm[];
    uint32_t* smu = (uint32_t*)sm;
    const int tid  = threadIdx.x;
    const int lane = tid & 31;
    const int wid  = tid >> 5;     // 0..15

    const int mtile = blockIdx.x & 1;       // 2 x 128-row tiles per problem
    const int pid   = blockIdx.x >> 1;      // 64 problems
    const int b     = pid >> 4;
    const int seg   = pid & 15;

    const long segbase = (long)b * NTOK + (long)seg * SEGW;  // token base
    const int  m0 = mtile * TM;             // offset into 256 gathered rows

    // Warp layout (both GEMMs): 4 m-warps x 4 n-warps
    const int wm  = wid & 3;
    const int wn  = wid >> 2;
    const int ln4 = lane >> 2;   // fragment group 0..7
    const int lc4 = lane & 3;    // thread-in-group 0..3

    // ============ Phase 1: S = Q K^T (128 x 256), double-buffered K chunks ============
    // Warp tile: 32 rows x 64 cols -> mt in {0,1}, nt in 0..7
    float acc[2][8][4];
    #pragma unroll
    for (int mt = 0; mt < 2; mt++)
        #pragma unroll
        for (int nt = 0; nt < 8; nt++)
            #pragma unroll
            for (int i = 0; i < 4; i++)
                acc[mt][nt][i] = 0.f;

    // Prologue: chunk 0 -> buf0 (tf32-rounded at store)
    #pragma unroll
    for (int j = 0; j < 4; j++) {
        int idx = j * THREADS + tid;
        int r = idx >> 3, c4 = idx & 7;
        float4 v = *(const float4*)(x + (size_t)(segbase + 2 * r) * DIM + c4 * 4);
        sts_tf32x4(sm + r * K_STRIDE + c4 * 4, v);
    }
    __syncthreads();

    float4 stg[4];
    for (int kc = 0; kc < NCHUNK; kc++) {
        const uint32_t* cur = smu + (kc & 1 ? KCHF : 0);
        const bool pf = (kc + 1 < NCHUNK);
        if (pf) {
            const int kd = (kc + 1) * KC;
            #pragma unroll
            for (int j = 0; j < 4; j++) {
                int idx = j * THREADS + tid;
                int r = idx >> 3, c4 = idx & 7;
                stg[j] = *(const float4*)(x + (size_t)(segbase + 2 * r) * DIM + kd + c4 * 4);
            }
        }
        const uint32_t* abase = cur + (m0 + wm * 32 + ln4) * K_STRIDE + lc4;
        const uint32_t* bbase = cur + (wn * 64 + ln4) * K_STRIDE + lc4;
        #pragma unroll
        for (int ks = 0; ks < KC / 8; ks++) {
            const int kk = ks * 8;
            uint32_t a[2][4];
            #pragma unroll
            for (int mt = 0; mt < 2; mt++) {
                const uint32_t* ba = abase + mt * 16 * K_STRIDE + kk;
                a[mt][0] = ba[0];
                a[mt][1] = ba[8 * K_STRIDE];
                a[mt][2] = ba[4];
                a[mt][3] = ba[8 * K_STRIDE + 4];
            }
            #pragma unroll
            for (int nt = 0; nt < 8; nt++) {
                const uint32_t* bb = bbase + nt * 8 * K_STRIDE + kk;
                uint32_t bf[2] = { bb[0], bb[4] };
                mma8(acc[0][nt], a[0], bf);
                mma8(acc[1][nt], a[1], bf);
            }
        }
        if (pf) {
            float* dst = sm + (kc & 1 ? 0 : KCHF);
            #pragma unroll
            for (int j = 0; j < 4; j++) {
                int idx = j * THREADS + tid;
                int r = idx >> 3, c4 = idx & 7;
                sts_tf32x4(dst + r * K_STRIDE + c4 * 4, stg[j]);
            }
        }
        __syncthreads();
    }

    // ============ Phase 2: scale + softmax into P (tf32-rounded on final write) ============
    const float scale = 0.03608439182435161f;  // 768^-0.5
    #pragma unroll
    for (int mt = 0; mt < 2; mt++)
        #pragma unroll
        for (int nt = 0; nt < 8; nt++) {
            int r = wm * 32 + mt * 16 + ln4;
            int c = wn * 64 + nt * 8 + 2 * lc4;
            sm[P_OFF + r * P_STRIDE + c]           = acc[mt][nt][0] * scale;
            sm[P_OFF + r * P_STRIDE + c + 1]       = acc[mt][nt][1] * scale;
            sm[P_OFF + (r + 8) * P_STRIDE + c]     = acc[mt][nt][2] * scale;
            sm[P_OFF + (r + 8) * P_STRIDE + c + 1] = acc[mt][nt][3] * scale;
        }
    __syncthreads();

    // Row softmax: warp w handles rows w*8..w*8+7 (128 rows, 16 warps)
    #pragma unroll
    for (int rr = 0; rr < 8; rr++) {
        int row = wid * 8 + rr;
        float* pr = sm + P_OFF + row * P_STRIDE;
        float v[8];
        float mx = -1e30f;
        #pragma unroll
        for (int i = 0; i < 8; i++) { v[i] = pr[lane + 32 * i]; mx = fmaxf(mx, v[i]); }
        #pragma unroll
        for (int o = 16; o > 0; o >>= 1) mx = fmaxf(mx, __shfl_xor_sync(~0u, mx, o));
        float s = 0.f;
        #pragma unroll
        for (int i = 0; i < 8; i++) { v[i] = expf(v[i] - mx); s += v[i]; }
        #pragma unroll
        for (int o = 16; o > 0; o >>= 1) s += __shfl_xor_sync(~0u, s, o);
        float inv = 1.f / s;
        #pragma unroll
        for (int i = 0; i < 8; i++)
            pr[lane + 32 * i] = __uint_as_float(f2tf32(v[i] * inv));
    }
    __syncthreads();

    // ============ Phase 3: out = P V (128 x 768), 4 d-chunks of 192, V in 32-row slabs ============
    for (int ch = 0; ch < 4; ch++) {
        const int d0 = ch * DCH;

        // Warp tile: 32 rows x 48 cols -> mt in {0,1}, nt in 0..5
        float o[2][6][4];
        #pragma unroll
        for (int mt = 0; mt < 2; mt++)
            #pragma unroll
            for (int nt = 0; nt < 6; nt++)
                #pragma unroll
                for (int i = 0; i < 4; i++)
                    o[mt][nt][i] = 0.f;

        // Prologue: slab 0 -> V buf0
        #pragma unroll
        for (int j = 0; j < 3; j++) {
            int idx = j * THREADS + tid;
            int row = idx / 48, c4 = idx % 48;
            float4 v = *(const float4*)(x + (size_t)(segbase + 2 * row) * DIM + d0 + c4 * 4);
            sts_tf32x4(sm + V_OFF + row * V_STRIDE + c4 * 4, v);
        }
        __syncthreads();

        float4 vst[3];
        for (int sl = 0; sl < NSLAB; sl++) {
            const uint32_t* vcur = smu + V_OFF + (sl & 1) * VSLABF;
            const bool pf = (sl + 1 < NSLAB);
            if (pf) {
                const int rbase = (sl + 1) * KSLAB;
                #pragma unroll
                for (int j = 0; j < 3; j++) {
                    int idx = j * THREADS + tid;
                    int row = idx / 48, c4 = idx % 48;
                    vst[j] = *(const float4*)(x + (size_t)(segbase + 2 * (rbase + row)) * DIM + d0 + c4 * 4);
                }
            }
            const uint32_t* abase0 = smu + P_OFF + (wm * 32 + ln4) * P_STRIDE + sl * KSLAB + lc4;
            const uint32_t* bbase0 = vcur + lc4 * V_STRIDE + wn * 48 + ln4;
            #pragma unroll
            for (int ks = 0; ks < KSLAB / 8; ks++) {
                const int kk = ks * 8;
                uint32_t a[2][4];
                #pragma unroll
                for (int mt = 0; mt < 2; mt++) {
                    const uint32_t* ba = abase0 + mt * 16 * P_STRIDE + kk;
                    a[mt][0] = ba[0];
                    a[mt][1] = ba[8 * P_STRIDE];
                    a[mt][2] = ba[4];
                    a[mt][3] = ba[8 * P_STRIDE + 4];
                }
                const uint32_t* bb0 = bbase0 + kk * V_STRIDE;
                #pragma unroll
                for (int nt = 0; nt < 6; nt++) {
                    const uint32_t* bb = bb0 + nt * 8;
                    uint32_t bf[2] = { bb[0], bb[4 * V_STRIDE] };
                    mma8(o[0][nt], a[0], bf);
                    mma8(o[1][nt], a[1], bf);
                }
            }
            if (pf) {
                float* dst = sm + V_OFF + ((sl + 1) & 1) * VSLABF;
                #pragma unroll
                for (int j = 0; j < 3; j++) {
                    int idx = j * THREADS + tid;
                    int row = idx / 48, c4 = idx % 48;
                    sts_tf32x4(dst + row * V_STRIDE + c4 * 4, vst[j]);
                }
            }
            __syncthreads();
        }

        // Epilogue: even (gathered) rows get results
        #pragma unroll
        for (int mt = 0; mt < 2; mt++)
            #pragma unroll
            for (int nt = 0; nt < 6; nt++) {
                int gr = m0 + wm * 32 + mt * 16 + ln4;
                int c  = d0 + wn * 48 + nt * 8 + 2 * lc4;
                long tok0 = segbase + 2 * (long)gr;
                long tok1 = segbase + 2 * (long)(gr + 8);
                *(float2*)(y + (size_t)tok0 * DIM + c) = make_float2(o[mt][nt][0], o[mt][nt][1]);
                *(float2*)(y + (size_t)tok1 * DIM + c) = make_float2(o[mt][nt][2], o[mt][nt][3]);
            }

        // Odd partner rows are exactly zero (this d-chunk)
        #pragma unroll
        for (int j = 0; j < 12; j++) {
            int i = j * THREADS + tid;
            int r = i / 48, c4 = i % 48;
            long tok = segbase + 2 * (long)(m0 + r) + 1;
            *(float4*)(y + (size_t)tok * DIM + d0 + c4 * 4) = make_float4(0.f, 0.f, 0.f, 0.f);
        }
        __syncthreads();
    }
}

extern "C" void kernel_launch(void* const* d_in, const int* in_sizes, int n_in,
                              void* d_out, int out_size)
{
    const float* x = (const float*)d_in[0];
    float* y = (float*)d_out;
    cudaFuncSetAttribute(dilated_attn_kernel,
                         cudaFuncAttributeMaxDynamicSharedMemorySize, SMEM_BYTES);
    dilated_attn_kernel<<<BATCH * NSEG * 2, THREADS, SMEM_BYTES>>>(x, y);
}